// round 11
// baseline (speedup 1.0000x reference)
#include <cuda_runtime.h>
#include <stdint.h>

// Binarized depthwise 3x3 conv, stride 1, SAME. x:(16,112,112,256) NHWC fp32,
// kernel:(3,3,256,1). out = sum over valid taps of sign(x)*sign(k).
//
// Two-pass stream-purity design with BIT-SLICED CSA arithmetic:
//  Pass 1 (read-pure): x (205 MB) -> 1 sign bit/elem into 6.4 MB scratch
//    (byte per 8 channels; thread extracts 8 sign bits, no ballot).
//  Pass 2 (write-pure): scratch stays L2-resident. Per 32-channel word:
//    tap_i = (x_word ^ k_word) & rowmask   (1 LOP3 each, 9 taps)
//    CSA adder tree -> 4 count bit-planes (25 LOP3 / 32 ch / column)
//    out = T - 2*count, built per channel-pair via halfword SIMD +
//    PRMT into float magic 0x4B000000, one FADD. All exact integers.

#define NN 16
#define HH 112
#define WW 112
#define CC 256

// Packed signs: word index = ((n*HH+h)*WW + w)*8 + g, bit l = sign(ch 32g+l)<0
__device__ uint32_t g_sbits[(size_t)NN * HH * WW * 8];

// ---------------- Pass 1: sign-pack (read-pure) ----------------
__global__ __launch_bounds__(256, 8)
void pack_kernel(const float* __restrict__ x) {
    const int h = blockIdx.x;
    const int n = blockIdx.y;
    const int lane = threadIdx.x & 31;      // c8 group 0..31
    const int warp = threadIdx.x >> 5;      // w strip 0..7 (14 cols each)

    const uint32_t* px = (const uint32_t*)(x + ((size_t)(n * HH + h) * WW) * CC) + lane * 8;
    uint8_t* po = (uint8_t*)g_sbits + ((size_t)(n * HH + h) * WW) * 32 + lane;

    const int w0 = warp * 14;
#pragma unroll 7
    for (int i = 0; i < 14; ++i) {
        const int w = w0 + i;
        const uint4 a = *(const uint4*)(px + (size_t)w * CC);
        const uint4 b = *(const uint4*)(px + (size_t)w * CC + 4);
        const uint32_t s = (a.x >> 31) | ((a.y >> 31) << 1) | ((a.z >> 31) << 2) | ((a.w >> 31) << 3)
                         | ((b.x >> 31) << 4) | ((b.y >> 31) << 5) | ((b.z >> 31) << 6) | ((b.w >> 31) << 7);
        po[(size_t)w * 32] = (uint8_t)s;
    }
}

// ---------------- Pass 2: CSA conv from bits (write-pure) ----------------

// Convert 4 count bit-planes (32 channels) to 32 fp32 outputs and store.
// TT = (T+16) in both halfwords; value = T - 2*cnt, exact.
__device__ __forceinline__ void conv_store(uint32_t s0, uint32_t s1, uint32_t s2, uint32_t s3,
                                           uint32_t TT, float* __restrict__ o) {
    const uint32_t M = 0x00010001u;
#pragma unroll
    for (int r = 0; r < 4; ++r) {
        float lo[4], hi[4];
#pragma unroll
        for (int j = 0; j < 4; ++j) {
            const int l = 4 * r + j;   // channel pair (l, l+16)
            const uint32_t c2 = ((s0 >> l) & M) + (((s1 >> l) & M) << 1)
                              + (((s2 >> l) & M) << 2) + (((s3 >> l) & M) << 3);
            const uint32_t v = TT - (c2 << 1);   // per-halfword T+16-2c, in [7,25]
            lo[j] = __uint_as_float(__byte_perm(v, 0x4B000000u, 0x7440)) - 8388624.0f;
            hi[j] = __uint_as_float(__byte_perm(v, 0x4B000000u, 0x7442)) - 8388624.0f;
        }
        *(float4*)(o + 4 * r)      = make_float4(lo[0], lo[1], lo[2], lo[3]);
        *(float4*)(o + 16 + 4 * r) = make_float4(hi[0], hi[1], hi[2], hi[3]);
    }
}

// Compute column partial counts P_kw (2-bit planes) for column c.
#define COLP(c)                                                                 \
    {                                                                           \
        const uint32_t r0 = p0[(size_t)(c) * 8];                                \
        const uint32_t r1 = p1[(size_t)(c) * 8];                                \
        const uint32_t r2 = p2[(size_t)(c) * 8];                                \
        _Pragma("unroll")                                                       \
        for (int kwi = 0; kwi < 3; ++kwi) {                                     \
            const uint32_t t0 = (r0 ^ kw[0][kwi]) & m0;                         \
            const uint32_t t1 =  r1 ^ kw[1][kwi];                               \
            const uint32_t t2 = (r2 ^ kw[2][kwi]) & m2;                         \
            const uint32_t x01 = t0 ^ t1;                                       \
            Pl[kwi] = x01 ^ t2;                                                 \
            Ph[kwi] = (t0 & t1) | (t2 & x01);                                   \
        }                                                                       \
    }

// A = B + P1 (2-bit + 2-bit -> 3-bit), then B = P0.
#define UPDATE_AB()                                                             \
    {                                                                           \
        const uint32_t e0 = Blo & Pl[1];                                        \
        const uint32_t x1 = Bhi ^ Ph[1];                                        \
        a0 = Blo ^ Pl[1];                                                       \
        a1 = x1 ^ e0;                                                           \
        a2 = (Bhi & Ph[1]) | (e0 & x1);                                         \
        Blo = Pl[0]; Bhi = Ph[0];                                               \
    }

__global__ __launch_bounds__(256, 4)
void conv_kernel(const float* __restrict__ k, float* __restrict__ out) {
    __shared__ uint32_t skw[9][8];   // kernel sign words: [tap][c32 group]
    const int n = blockIdx.y;
    const int hquad = blockIdx.x >> 1;
    const int half = blockIdx.x & 1;
    const int lane = threadIdx.x & 31;
    const int warp = threadIdx.x >> 5;

    // Build 72 kernel sign words cooperatively (ballot over channel lanes).
    for (int idx = warp; idx < 72; idx += 8) {
        const int tap = idx >> 3, g = idx & 7;
        const uint32_t b = __ballot_sync(0xFFFFFFFFu, k[tap * CC + g * 32 + lane] < 0.0f);
        if (lane == 0) skw[tap][g] = b;
    }
    __syncthreads();

    const int g = lane & 7;          // c32 group 0..7
    const int row = lane >> 3;       // 4 h-rows per block
    const int h = hquad * 4 + row;
    const bool hasT = (h > 0);
    const bool hasB = (h < HH - 1);
    const uint32_t m0 = hasT ? 0xFFFFFFFFu : 0u;
    const uint32_t m2 = hasB ? 0xFFFFFFFFu : 0u;

    uint32_t kw[3][3];
#pragma unroll
    for (int kh = 0; kh < 3; ++kh)
#pragma unroll
        for (int kwi = 0; kwi < 3; ++kwi)
            kw[kh][kwi] = skw[kh * 3 + kwi][g];

    const int Trow = 1 + (int)hasT + (int)hasB;
    const uint32_t TTi = (uint32_t)(3 * Trow + 16) * 0x00010001u;  // interior cols
    const uint32_t TTe = (uint32_t)(2 * Trow + 16) * 0x00010001u;  // w=0 / w=111

    const uint32_t* p1 = g_sbits + ((size_t)(n * HH + h) * WW) * 8 + g;
    const uint32_t* p0 = hasT ? p1 - WW * 8 : p1;   // masked via m0
    const uint32_t* p2 = hasB ? p1 + WW * 8 : p1;   // masked via m2
    float* o = out + ((size_t)(n * HH + h) * WW) * CC + g * 32;

    const int strip = half * 8 + warp;   // warp-uniform: 16 strips of 7 cols
    const int ws = strip * 7;
    const int we = ws + 7;
    const int cbeg = (ws == 0) ? 0 : ws - 1;
    const int cend = (we == WW) ? WW - 1 : we;

    uint32_t Pl[3], Ph[3];
    uint32_t Blo, Bhi, a0, a1, a2;

    // Peel first column: init A = P1 (B was 0), B = P0.
    COLP(cbeg);
    a0 = Pl[1]; a1 = Ph[1]; a2 = 0u;
    Blo = Pl[0]; Bhi = Ph[0];

    int c = cbeg + 1;
    if (ws != 0) {            // extra no-store column so out[ws] gets P0(ws-1)
        COLP(c);
        UPDATE_AB();
        ++c;
    }

    uint32_t TT = (ws == 0) ? TTe : TTi;   // only w=0 output is a column edge
    for (; c <= cend; ++c) {
        COLP(c);
        // out(c-1) = A + P2(c): 3-bit + 2-bit -> 4 planes
        const uint32_t c0 = a0 & Pl[2];
        const uint32_t x1 = a1 ^ Ph[2];
        const uint32_t s0 = a0 ^ Pl[2];
        const uint32_t s1 = x1 ^ c0;
        const uint32_t c1 = (a1 & Ph[2]) | (c0 & x1);
        const uint32_t s2 = a2 ^ c1;
        const uint32_t s3 = a2 & c1;
        conv_store(s0, s1, s2, s3, TT, o + (size_t)(c - 1) * CC);
        TT = TTi;
        UPDATE_AB();
    }

    if (we == WW) {           // right edge: out[111] = P0(110)+P1(111) = A
        conv_store(a0, a1, a2, 0u, TTe, o + (size_t)(WW - 1) * CC);
    }
}

extern "C" void kernel_launch(void* const* d_in, const int* in_sizes, int n_in,
                              void* d_out, int out_size) {
    const float* x = (const float*)d_in[0];
    const float* k = (const float*)d_in[1];
    float* out = (float*)d_out;
    dim3 grid1(HH, NN);
    pack_kernel<<<grid1, 256>>>(x);
    dim3 grid2(56, NN);   // 56 = 28 h-quads x 2 strip-halves
    conv_kernel<<<grid2, 256>>>(k, out);
}

// round 12
// speedup vs baseline: 2.3026x; 2.3026x over previous
#include <cuda_runtime.h>
#include <stdint.h>

// Binarized depthwise 3x3 conv, stride 1, SAME. x:(16,112,112,256) NHWC fp32,
// kernel:(3,3,256,1). out = sum over valid taps of sign(x)*sign(k).
//
// bf16x2 math (exact, |sum|<=9): carrier = PRMT of two fp32 high halves;
// tap = (carrier & 0x80008000) ^ kp  (kp = bf16x2 +-1.0, 0 for missing
// border rows -> +-0.0 no-op under add.rn.bf16x2). Column recurrence:
//   out[c-1] = A + q2(c); A = B + q1(c); B = q0(c)
//
// NEW: cp.async (LDGSTS) column pipeline into an SMEM ring, depth D=8.
// Rationale: all LDG variants pinned at ~5.7 TB/s because per-warp
// scoreboard slots cap in-flight read bytes below the BW*latency product.
// LDGSTS has no depth cap -> ~28KB outstanding per CTA covers DRAM latency.
// CTA = (row-pair, 56-col strip); 128 thr = 64 quads x 2 output rows; the
// 4-row input band is staged per column; each thread computes one output row.

#define NN 16
#define HH 112
#define WW 112
#define CC 256
#define RS (WW * CC)
#define D  8              // pipeline stages (4KB each, 32KB total)

__device__ __forceinline__ uint32_t badd(uint32_t a, uint32_t b) {
    uint32_t r;
    asm("add.rn.bf16x2 %0, %1, %2;" : "=r"(r) : "r"(a), "r"(b));
    return r;
}

#define TAPP(t, kp) ((((t) & 0x80008000u)) ^ (kp))

__device__ __forceinline__ void carr(const uint4 v, uint32_t& a, uint32_t& b) {
    a = __byte_perm(v.x, v.y, 0x7632);
    b = __byte_perm(v.z, v.w, 0x7632);
}

__device__ __forceinline__ void store4(float* __restrict__ p,
                                       uint32_t oa, uint32_t ob) {
    float4 o4;
    o4.x = __uint_as_float(oa << 16);
    o4.y = __uint_as_float(oa & 0xFFFF0000u);
    o4.z = __uint_as_float(ob << 16);
    o4.w = __uint_as_float(ob & 0xFFFF0000u);
    *reinterpret_cast<float4*>(p) = o4;
}

__global__ __launch_bounds__(128, 6)
void bconv_kernel(const float* __restrict__ x,
                  const float* __restrict__ k,
                  float* __restrict__ out) {
    __shared__ uint4 stage[D][4][64];   // [slot][band row][channel quad]

    const int hpair = blockIdx.x >> 1;  // 0..55
    const int strip = blockIdx.x & 1;   // two 56-col strips
    const int n = blockIdx.y;
    const int t = threadIdx.x;
    const int q = t & 63;               // channel quad
    const int rr = t >> 6;              // output row within pair (0/1)

    const int h0 = hpair * 2;
    const int h = h0 + rr;              // my output row
    const int c0 = q * 4;

    // Kernel signs for MY output row; zero outer taps at image borders.
    const bool zt = (h == 0);
    const bool zb = (h == HH - 1);
    uint32_t kp[3][3][2];
#pragma unroll
    for (int kh = 0; kh < 3; ++kh) {
        const bool zz = (kh == 0 && zt) || (kh == 2 && zb);
#pragma unroll
        for (int kw = 0; kw < 3; ++kw) {
            const float4 kv = *reinterpret_cast<const float4*>(k + (kh * 3 + kw) * CC + c0);
            uint32_t s0 = (kv.x >= 0.0f) ? 0x3F80u : 0xBF80u;
            uint32_t s1 = (kv.y >= 0.0f) ? 0x3F80u : 0xBF80u;
            uint32_t s2 = (kv.z >= 0.0f) ? 0x3F80u : 0xBF80u;
            uint32_t s3 = (kv.w >= 0.0f) ? 0x3F80u : 0xBF80u;
            kp[kh][kw][0] = zz ? 0u : (s0 | (s1 << 16));
            kp[kh][kw][1] = zz ? 0u : (s2 | (s3 << 16));
        }
    }

    // Loader role: thread loads band rows 2rr, 2rr+1 (band = h0-1..h0+2,
    // clamped at borders; clamped rows' contributions are zeroed via kp).
    int lr0 = h0 - 1 + 2 * rr; if (lr0 < 0) lr0 = 0;
    int lr1 = h0 + 2 * rr;     if (lr1 > HH - 1) lr1 = HH - 1;
    const float* L0 = x + ((size_t)n * HH + lr0) * RS + c0;
    const float* L1 = x + ((size_t)n * HH + lr1) * RS + c0;
    float*       o  = out + ((size_t)n * HH + h) * RS + c0;

    const int ws = strip * 56;
    const int we = ws + 56;
    const int cbeg = (ws == 0) ? 0 : ws - 1;
    const int cend = (we == WW) ? WW - 1 : we;
    const int sfirst = ws + 1;          // first column whose iter stores

    // SMEM byte addresses for my two destination rows (slot 0).
    const uint32_t sbase = (uint32_t)__cvta_generic_to_shared(&stage[0][0][0]);
    const uint32_t myd0 = sbase + ((2 * rr) * 64 + q) * 16;
    const uint32_t myd1 = myd0 + 64 * 16;

    // ---- prologue: fill D-1 stages ----
#pragma unroll
    for (int p = 0; p < D - 1; ++p) {
        const int c = cbeg + p;                     // 57 cols >= D-1, always valid
        const uint32_t d0 = myd0 + p * (4 * 64 * 16);
        const uint32_t d1 = myd1 + p * (4 * 64 * 16);
        asm volatile("cp.async.cg.shared.global [%0], [%1], 16;"
                     :: "r"(d0), "l"(L0 + (size_t)c * CC) : "memory");
        asm volatile("cp.async.cg.shared.global [%0], [%1], 16;"
                     :: "r"(d1), "l"(L1 + (size_t)c * CC) : "memory");
        asm volatile("cp.async.commit_group;" ::: "memory");
    }

    uint32_t Aa = 0, Ab = 0, Ba = 0, Bb = 0;
    int slot = 0;

    for (int c = cbeg; c <= cend; ++c) {
        asm volatile("cp.async.wait_group %0;" :: "n"(D - 2) : "memory");
        __syncthreads();                 // stage `slot` visible to all

        uint32_t t0a, t0b, t1a, t1b, t2a, t2b;
        carr(stage[slot][rr][q],     t0a, t0b);
        carr(stage[slot][rr + 1][q], t1a, t1b);
        carr(stage[slot][rr + 2][q], t2a, t2b);

        const uint32_t q0a = badd(badd(TAPP(t0a, kp[0][0][0]), TAPP(t1a, kp[1][0][0])), TAPP(t2a, kp[2][0][0]));
        const uint32_t q0b = badd(badd(TAPP(t0b, kp[0][0][1]), TAPP(t1b, kp[1][0][1])), TAPP(t2b, kp[2][0][1]));
        const uint32_t q1a = badd(badd(TAPP(t0a, kp[0][1][0]), TAPP(t1a, kp[1][1][0])), TAPP(t2a, kp[2][1][0]));
        const uint32_t q1b = badd(badd(TAPP(t0b, kp[0][1][1]), TAPP(t1b, kp[1][1][1])), TAPP(t2b, kp[2][1][1]));
        const uint32_t q2a = badd(badd(TAPP(t0a, kp[0][2][0]), TAPP(t1a, kp[1][2][0])), TAPP(t2a, kp[2][2][0]));
        const uint32_t q2b = badd(badd(TAPP(t0b, kp[0][2][1]), TAPP(t1b, kp[1][2][1])), TAPP(t2b, kp[2][2][1]));

        if (c == cbeg) {
            Aa = q1a; Ab = q1b; Ba = q0a; Bb = q0b;
        } else {
            if (c >= sfirst)             // uniform; no cross-strip overlap
                store4(o + (size_t)(c - 1) * CC, badd(Aa, q2a), badd(Ab, q2b));
            Aa = badd(Ba, q1a); Ba = q0a;
            Ab = badd(Bb, q1b); Bb = q0b;
        }

        __syncthreads();                 // all reads of the reuse slot done

        const int cn = c + D - 1;
        if (cn <= cend) {
            const int sl2 = (slot == 0) ? D - 1 : slot - 1;  // (slot+D-1)%D
            const uint32_t d0 = myd0 + sl2 * (4 * 64 * 16);
            const uint32_t d1 = myd1 + sl2 * (4 * 64 * 16);
            asm volatile("cp.async.cg.shared.global [%0], [%1], 16;"
                         :: "r"(d0), "l"(L0 + (size_t)cn * CC) : "memory");
            asm volatile("cp.async.cg.shared.global [%0], [%1], 16;"
                         :: "r"(d1), "l"(L1 + (size_t)cn * CC) : "memory");
        }
        asm volatile("cp.async.commit_group;" ::: "memory");  // keep counts uniform

        slot = (slot + 1 == D) ? 0 : slot + 1;
    }

    if (we == WW)  // right edge: out[111] = q0(110) + q1(111) = A
        store4(o + (size_t)(WW - 1) * CC, Aa, Ab);
}

extern "C" void kernel_launch(void* const* d_in, const int* in_sizes, int n_in,
                              void* d_out, int out_size) {
    const float* x = (const float*)d_in[0];
    const float* k = (const float*)d_in[1];
    float* out = (float*)d_out;
    dim3 grid(112, NN);   // 56 row-pairs x 2 strips
    bconv_kernel<<<grid, 128>>>(x, k, out);
}

// round 13
// speedup vs baseline: 2.3590x; 1.0245x over previous
#include <cuda_runtime.h>
#include <stdint.h>

// Binarized depthwise 3x3 conv, stride 1, SAME. x:(16,112,112,256) NHWC fp32,
// kernel:(3,3,256,1). out = sum over valid taps of sign(x)*sign(k).
//
// bf16x2 math (exact, |sum|<=9): carrier = PRMT of two fp32 high halves;
// tap = (carrier & 0x80008000) ^ kp (kp = bf16x2 +-1.0; 0 for missing border
// rows -> +-0.0 no-op under add.rn.bf16x2). Column recurrence:
//   out[c-1] = A + q2(c); A = B + q1(c); B = q0(c)
//
// cp.async column pipeline (depth D=8) into WARP-PRIVATE smem: each warp owns
// 64 channels x both rows of a row-pair, loads its own 4-row band, and syncs
// with wait_group + __syncwarp only -- zero __syncthreads in the hot loop
// (R12 paid 2 block barriers per column). Slot written at column c was read
// at column c-1, so one syncwarp per column is sufficient.

#define NN 16
#define HH 112
#define WW 112
#define CC 256
#define RS (WW * CC)
#define D  8                     // pipeline stages; 1KB/stage/warp

__device__ __forceinline__ uint32_t badd(uint32_t a, uint32_t b) {
    uint32_t r;
    asm("add.rn.bf16x2 %0, %1, %2;" : "=r"(r) : "r"(a), "r"(b));
    return r;
}

#define TAPP(t, kp) ((((t) & 0x80008000u)) ^ (kp))

__device__ __forceinline__ void carr(const uint4 v, uint32_t& a, uint32_t& b) {
    a = __byte_perm(v.x, v.y, 0x7632);
    b = __byte_perm(v.z, v.w, 0x7632);
}

__device__ __forceinline__ void store4(float* __restrict__ p,
                                       uint32_t oa, uint32_t ob) {
    float4 o4;
    o4.x = __uint_as_float(oa << 16);
    o4.y = __uint_as_float(oa & 0xFFFF0000u);
    o4.z = __uint_as_float(ob << 16);
    o4.w = __uint_as_float(ob & 0xFFFF0000u);
    *reinterpret_cast<float4*>(p) = o4;
}

__global__ __launch_bounds__(128, 6)
void bconv_kernel(const float* __restrict__ x,
                  const float* __restrict__ k,
                  float* __restrict__ out) {
    // [warp][slot][band row][quad] -- each warp touches only its own slice.
    __shared__ uint4 stage[4][D][4][16];

    const int hpair = blockIdx.x >> 1;   // 0..55
    const int strip = blockIdx.x & 1;    // two 56-col strips
    const int n = blockIdx.y;
    const int t = threadIdx.x;
    const int w = t >> 5;                // warp: channel group (64 ch)
    const int lid = t & 31;
    const int ql = lid & 15;             // quad within warp
    const int rr = lid >> 4;             // output row within pair (0/1)

    const int h0 = hpair * 2;
    const int h = h0 + rr;               // my output row
    const int c0 = (w * 16 + ql) * 4;    // first channel of my quad

    // Kernel signs for MY output row; zero outer taps at image borders.
    const bool zt = (h == 0);
    const bool zb = (h == HH - 1);
    uint32_t kp[3][3][2];
#pragma unroll
    for (int kh = 0; kh < 3; ++kh) {
        const bool zz = (kh == 0 && zt) || (kh == 2 && zb);
#pragma unroll
        for (int kw = 0; kw < 3; ++kw) {
            const float4 kv = *reinterpret_cast<const float4*>(k + (kh * 3 + kw) * CC + c0);
            uint32_t s0 = (kv.x >= 0.0f) ? 0x3F80u : 0xBF80u;
            uint32_t s1 = (kv.y >= 0.0f) ? 0x3F80u : 0xBF80u;
            uint32_t s2 = (kv.z >= 0.0f) ? 0x3F80u : 0xBF80u;
            uint32_t s3 = (kv.w >= 0.0f) ? 0x3F80u : 0xBF80u;
            kp[kh][kw][0] = zz ? 0u : (s0 | (s1 << 16));
            kp[kh][kw][1] = zz ? 0u : (s2 | (s3 << 16));
        }
    }

    // Loader role: thread loads band rows 2rr, 2rr+1 (band = h0-1..h0+2,
    // clamped; clamped rows' contributions are zeroed via kp).
    int lr0 = h0 - 1 + 2 * rr; if (lr0 < 0) lr0 = 0;
    int lr1 = h0 + 2 * rr;     if (lr1 > HH - 1) lr1 = HH - 1;
    const float* L0 = x + ((size_t)n * HH + lr0) * RS + c0;
    const float* L1 = x + ((size_t)n * HH + lr1) * RS + c0;
    float*       o  = out + ((size_t)n * HH + h) * RS + c0;

    const int ws = strip * 56;
    const int we = ws + 56;
    const int cbeg = (ws == 0) ? 0 : ws - 1;
    const int cend = (we == WW) ? WW - 1 : we;
    const int sfirst = ws + 1;           // first column whose iter stores

    // SMEM byte addresses (my warp's slice); slot stride = 1KB.
    const uint32_t sbase = (uint32_t)__cvta_generic_to_shared(&stage[w][0][0][0]);
    const uint32_t myd0 = sbase + ((2 * rr) * 16 + ql) * 16;
    const uint32_t myd1 = myd0 + 256;

    // ---- prologue: fill D-1 stages ----
#pragma unroll
    for (int p = 0; p < D - 1; ++p) {
        const int c = cbeg + p;          // 57 cols >= D-1, always valid
        asm volatile("cp.async.cg.shared.global [%0], [%1], 16;"
                     :: "r"(myd0 + p * 1024), "l"(L0 + (size_t)c * CC) : "memory");
        asm volatile("cp.async.cg.shared.global [%0], [%1], 16;"
                     :: "r"(myd1 + p * 1024), "l"(L1 + (size_t)c * CC) : "memory");
        asm volatile("cp.async.commit_group;" ::: "memory");
    }

    uint32_t Aa = 0, Ab = 0, Ba = 0, Bb = 0;
    int slot = 0;

    for (int c = cbeg; c <= cend; ++c) {
        asm volatile("cp.async.wait_group %0;" :: "n"(D - 2) : "memory");
        __syncwarp();                    // all warp lanes' loads for `slot` done

        uint32_t t0a, t0b, t1a, t1b, t2a, t2b;
        carr(stage[w][slot][rr][ql],     t0a, t0b);
        carr(stage[w][slot][rr + 1][ql], t1a, t1b);
        carr(stage[w][slot][rr + 2][ql], t2a, t2b);

        const uint32_t q0a = badd(badd(TAPP(t0a, kp[0][0][0]), TAPP(t1a, kp[1][0][0])), TAPP(t2a, kp[2][0][0]));
        const uint32_t q0b = badd(badd(TAPP(t0b, kp[0][0][1]), TAPP(t1b, kp[1][0][1])), TAPP(t2b, kp[2][0][1]));
        const uint32_t q1a = badd(badd(TAPP(t0a, kp[0][1][0]), TAPP(t1a, kp[1][1][0])), TAPP(t2a, kp[2][1][0]));
        const uint32_t q1b = badd(badd(TAPP(t0b, kp[0][1][1]), TAPP(t1b, kp[1][1][1])), TAPP(t2b, kp[2][1][1]));
        const uint32_t q2a = badd(badd(TAPP(t0a, kp[0][2][0]), TAPP(t1a, kp[1][2][0])), TAPP(t2a, kp[2][2][0]));
        const uint32_t q2b = badd(badd(TAPP(t0b, kp[0][2][1]), TAPP(t1b, kp[1][2][1])), TAPP(t2b, kp[2][2][1]));

        if (c == cbeg) {
            Aa = q1a; Ab = q1b; Ba = q0a; Bb = q0b;
        } else {
            if (c >= sfirst)             // uniform; no cross-strip overlap
                store4(o + (size_t)(c - 1) * CC, badd(Aa, q2a), badd(Ab, q2b));
            Aa = badd(Ba, q1a); Ba = q0a;
            Ab = badd(Bb, q1b); Bb = q0b;
        }

        // Refill: slot written here was read at column c-1 (readers done).
        const int cn = c + D - 1;
        if (cn <= cend) {
            const int sl2 = (slot == 0) ? D - 1 : slot - 1;   // (slot+D-1)%D
            asm volatile("cp.async.cg.shared.global [%0], [%1], 16;"
                         :: "r"(myd0 + sl2 * 1024), "l"(L0 + (size_t)cn * CC) : "memory");
            asm volatile("cp.async.cg.shared.global [%0], [%1], 16;"
                         :: "r"(myd1 + sl2 * 1024), "l"(L1 + (size_t)cn * CC) : "memory");
        }
        asm volatile("cp.async.commit_group;" ::: "memory");  // uniform counts

        slot = (slot + 1 == D) ? 0 : slot + 1;
    }

    if (we == WW)  // right edge: out[111] = q0(110) + q1(111) = A
        store4(o + (size_t)(WW - 1) * CC, Aa, Ab);
}

extern "C" void kernel_launch(void* const* d_in, const int* in_sizes, int n_in,
                              void* d_out, int out_size) {
    const float* x = (const float*)d_in[0];
    const float* k = (const float*)d_in[1];
    float* out = (float*)d_out;
    dim3 grid(112, NN);   // 56 row-pairs x 2 strips
    bconv_kernel<<<grid, 128>>>(x, k, out);
}

// round 15
// speedup vs baseline: 2.3706x; 1.0049x over previous
#include <cuda_runtime.h>
#include <stdint.h>

// Binarized depthwise 3x3 conv, stride 1, SAME. x:(16,112,112,256) NHWC fp32,
// kernel:(3,3,256,1). out = sum over valid taps of sign(x)*sign(k).
//
// bf16x2 math (exact, |sum|<=9): carrier = PRMT of two fp32 high halves;
// tap = (carrier & 0x80008000) ^ kp (kp = bf16x2 +-1.0; 0 for missing border
// rows -> +-0.0 no-op under add.rn.bf16x2). Column recurrence:
//   out[c-1] = A + q2(c); A = B + q1(c); B = q0(c)
//
// Warp-private cp.async pipeline, TWO-COLUMN stages (D=4 slots x 2 cols):
// one wait_group/syncwarp/commit per 2 columns. Pair p lives in slot p%D;
// refill target is (slot+D-1)%D == the slot read LAST iteration (fixed from
// R14, which refilled the current slot and left slot 3 never-loaded).

#define NN 16
#define HH 112
#define WW 112
#define CC 256
#define RS (WW * CC)
#define D  4                     // slots; each slot = 2 columns (2KB/warp)

__device__ __forceinline__ uint32_t badd(uint32_t a, uint32_t b) {
    uint32_t r;
    asm("add.rn.bf16x2 %0, %1, %2;" : "=r"(r) : "r"(a), "r"(b));
    return r;
}

#define TAPP(t, kp) ((((t) & 0x80008000u)) ^ (kp))

__device__ __forceinline__ void carr(const uint4 v, uint32_t& a, uint32_t& b) {
    a = __byte_perm(v.x, v.y, 0x7632);
    b = __byte_perm(v.z, v.w, 0x7632);
}

__device__ __forceinline__ void store4(float* __restrict__ p,
                                       uint32_t oa, uint32_t ob) {
    float4 o4;
    o4.x = __uint_as_float(oa << 16);
    o4.y = __uint_as_float(oa & 0xFFFF0000u);
    o4.z = __uint_as_float(ob << 16);
    o4.w = __uint_as_float(ob & 0xFFFF0000u);
    *reinterpret_cast<float4*>(p) = o4;
}

// Compute q0..q2 (both halves) for smem column (slotv, col2v).
#define COLQ(slotv, col2v)                                                                              \
    {                                                                                                   \
        uint32_t t0a, t0b, t1a, t1b, t2a, t2b;                                                          \
        carr(stage[w][slotv][col2v][rr][ql],     t0a, t0b);                                             \
        carr(stage[w][slotv][col2v][rr + 1][ql], t1a, t1b);                                             \
        carr(stage[w][slotv][col2v][rr + 2][ql], t2a, t2b);                                             \
        q0a = badd(badd(TAPP(t0a, kp[0][0][0]), TAPP(t1a, kp[1][0][0])), TAPP(t2a, kp[2][0][0]));        \
        q0b = badd(badd(TAPP(t0b, kp[0][0][1]), TAPP(t1b, kp[1][0][1])), TAPP(t2b, kp[2][0][1]));        \
        q1a = badd(badd(TAPP(t0a, kp[0][1][0]), TAPP(t1a, kp[1][1][0])), TAPP(t2a, kp[2][1][0]));        \
        q1b = badd(badd(TAPP(t0b, kp[0][1][1]), TAPP(t1b, kp[1][1][1])), TAPP(t2b, kp[2][1][1]));        \
        q2a = badd(badd(TAPP(t0a, kp[0][2][0]), TAPP(t1a, kp[1][2][0])), TAPP(t2a, kp[2][2][0]));        \
        q2b = badd(badd(TAPP(t0b, kp[0][2][1]), TAPP(t1b, kp[1][2][1])), TAPP(t2b, kp[2][2][1]));        \
    }

// Load 2-column pair `pairIdx` into slot `slotIdx` (4 cp.async per thread).
#define LOADPAIR(slotIdx, pairIdx)                                                                      \
    {                                                                                                   \
        const int cA = cbeg + 2 * (pairIdx);                                                            \
        const uint32_t dd = myd + (uint32_t)(slotIdx) * 2048u;                                          \
        asm volatile("cp.async.cg.shared.global [%0], [%1], 16;"                                        \
                     :: "r"(dd), "l"(L0 + (size_t)cA * CC) : "memory");                                 \
        asm volatile("cp.async.cg.shared.global [%0], [%1], 16;"                                        \
                     :: "r"(dd + 256u), "l"(L1 + (size_t)cA * CC) : "memory");                          \
        asm volatile("cp.async.cg.shared.global [%0], [%1], 16;"                                        \
                     :: "r"(dd + 1024u), "l"(L0 + (size_t)(cA + 1) * CC) : "memory");                   \
        asm volatile("cp.async.cg.shared.global [%0], [%1], 16;"                                        \
                     :: "r"(dd + 1280u), "l"(L1 + (size_t)(cA + 1) * CC) : "memory");                   \
    }

__global__ __launch_bounds__(128, 6)
void bconv_kernel(const float* __restrict__ x,
                  const float* __restrict__ k,
                  float* __restrict__ out) {
    // [warp][slot][col2][band row][quad]; warp-private slices.
    __shared__ uint4 stage[4][D][2][4][16];

    const int hpair = blockIdx.x >> 1;   // 0..55
    const int strip = blockIdx.x & 1;    // two 56-col strips
    const int n = blockIdx.y;
    const int t = threadIdx.x;
    const int w = t >> 5;                // warp: 64-channel group
    const int lid = t & 31;
    const int ql = lid & 15;             // quad within warp
    const int rr = lid >> 4;             // output row within pair (0/1)

    const int h0 = hpair * 2;
    const int h = h0 + rr;               // my output row
    const int c0 = (w * 16 + ql) * 4;    // first channel of my quad

    // Kernel signs for MY output row; zero outer taps at image borders.
    const bool zt = (h == 0);
    const bool zb = (h == HH - 1);
    uint32_t kp[3][3][2];
#pragma unroll
    for (int kh = 0; kh < 3; ++kh) {
        const bool zz = (kh == 0 && zt) || (kh == 2 && zb);
#pragma unroll
        for (int kw = 0; kw < 3; ++kw) {
            const float4 kv = *reinterpret_cast<const float4*>(k + (kh * 3 + kw) * CC + c0);
            uint32_t s0 = (kv.x >= 0.0f) ? 0x3F80u : 0xBF80u;
            uint32_t s1 = (kv.y >= 0.0f) ? 0x3F80u : 0xBF80u;
            uint32_t s2 = (kv.z >= 0.0f) ? 0x3F80u : 0xBF80u;
            uint32_t s3 = (kv.w >= 0.0f) ? 0x3F80u : 0xBF80u;
            kp[kh][kw][0] = zz ? 0u : (s0 | (s1 << 16));
            kp[kh][kw][1] = zz ? 0u : (s2 | (s3 << 16));
        }
    }

    // Loader role: thread loads band rows 2rr, 2rr+1 (band = h0-1..h0+2,
    // clamped; clamped rows' contributions are zeroed via kp).
    int lr0 = h0 - 1 + 2 * rr; if (lr0 < 0) lr0 = 0;
    int lr1 = h0 + 2 * rr;     if (lr1 > HH - 1) lr1 = HH - 1;
    const float* L0 = x + ((size_t)n * HH + lr0) * RS + c0;
    const float* L1 = x + ((size_t)n * HH + lr1) * RS + c0;
    float*       o  = out + ((size_t)n * HH + h) * RS + c0;

    const int ws = strip * 56;
    const int we = ws + 56;
    const int cbeg = (ws == 0) ? 0 : ws - 1;
    const int cend = (we == WW) ? WW - 1 : we;   // 57th (tail) column
    const int sfirst = ws + 1;           // first column whose iter stores

    // SMEM byte address of my (slot0, col0, row 2rr, quad) cell.
    const uint32_t sbase = (uint32_t)__cvta_generic_to_shared(&stage[w][0][0][0][0]);
    const uint32_t myd = sbase + ((2 * rr) * 16 + ql) * 16;

    // ---- prologue: pairs 0..D-2 into slots 0..D-2 ----
#pragma unroll
    for (int p = 0; p < D - 1; ++p) {
        LOADPAIR(p, p);
        asm volatile("cp.async.commit_group;" ::: "memory");
    }

    uint32_t Aa, Ab, Ba, Bb;
    uint32_t q0a, q0b, q1a, q1b, q2a, q2b;

    // ---- peeled pair 0 (slot 0; cols cbeg, cbeg+1) ----
    asm volatile("cp.async.wait_group %0;" :: "n"(D - 2) : "memory");
    __syncwarp();
    COLQ(0, 0);                           // c = cbeg: init only
    Aa = q1a; Ab = q1b; Ba = q0a; Bb = q0b;
    COLQ(0, 1);                           // c = cbeg+1
    if (cbeg + 1 >= sfirst)               // uniform (strip 0 stores out[0])
        store4(o + (size_t)cbeg * CC, badd(Aa, q2a), badd(Ab, q2b));
    Aa = badd(Ba, q1a); Ba = q0a;
    Ab = badd(Bb, q1b); Bb = q0b;
    LOADPAIR(D - 1, D - 1);               // pair D-1 -> slot D-1 (FIXED)
    asm volatile("cp.async.commit_group;" ::: "memory");

    // ---- main loop: pairs 1..27 (slot = p % D; always store) ----
    int slot = 1;
    for (int p = 1; p < 28; ++p) {
        asm volatile("cp.async.wait_group %0;" :: "n"(D - 2) : "memory");
        __syncwarp();
        const int c1 = cbeg + 2 * p;

        COLQ(slot, 0);                    // col c1: stores out[c1-1]
        store4(o + (size_t)(c1 - 1) * CC, badd(Aa, q2a), badd(Ab, q2b));
        Aa = badd(Ba, q1a); Ba = q0a;
        Ab = badd(Bb, q1b); Bb = q0b;

        COLQ(slot, 1);                    // col c1+1: stores out[c1]
        store4(o + (size_t)c1 * CC, badd(Aa, q2a), badd(Ab, q2b));
        Aa = badd(Ba, q1a); Ba = q0a;
        Ab = badd(Bb, q1b); Bb = q0b;

        // Refill pair p+D-1 -> slot (p+D-1)%D == (slot+D-1)%D, i.e. the slot
        // read LAST iteration (race-safe behind this iteration's syncwarp).
        if (p + D - 1 < 28) {             // uniform
            const int rslot = (slot + D - 1) & (D - 1);
            LOADPAIR(rslot, p + D - 1);
        }
        asm volatile("cp.async.commit_group;" ::: "memory");  // uniform counts
        slot = (slot + 1 == D) ? 0 : slot + 1;
    }

    // ---- tail column cend (direct LDG; 3 band rows for my output row) ----
    {
        const int cr0 = zt ? h : h - 1;   // clamped; zeroed via kp
        const int cr2 = zb ? h : h + 1;
        const float* R0 = x + ((size_t)n * HH + cr0) * RS + c0;
        const float* R1 = x + ((size_t)n * HH + h  ) * RS + c0;
        const float* R2 = x + ((size_t)n * HH + cr2) * RS + c0;
        uint32_t t0a, t0b, t1a, t1b, t2a, t2b;
        carr(*reinterpret_cast<const uint4*>(R0 + (size_t)cend * CC), t0a, t0b);
        carr(*reinterpret_cast<const uint4*>(R1 + (size_t)cend * CC), t1a, t1b);
        carr(*reinterpret_cast<const uint4*>(R2 + (size_t)cend * CC), t2a, t2b);
        q1a = badd(badd(TAPP(t0a, kp[0][1][0]), TAPP(t1a, kp[1][1][0])), TAPP(t2a, kp[2][1][0]));
        q1b = badd(badd(TAPP(t0b, kp[0][1][1]), TAPP(t1b, kp[1][1][1])), TAPP(t2b, kp[2][1][1]));
        q2a = badd(badd(TAPP(t0a, kp[0][2][0]), TAPP(t1a, kp[1][2][0])), TAPP(t2a, kp[2][2][0]));
        q2b = badd(badd(TAPP(t0b, kp[0][2][1]), TAPP(t1b, kp[1][2][1])), TAPP(t2b, kp[2][2][1]));
        store4(o + (size_t)(cend - 1) * CC, badd(Aa, q2a), badd(Ab, q2b));
        Aa = badd(Ba, q1a);
        Ab = badd(Bb, q1b);
    }

    if (we == WW)  // right edge: out[111] = q0(110) + q1(111) = A
        store4(o + (size_t)(WW - 1) * CC, Aa, Ab);
}

extern "C" void kernel_launch(void* const* d_in, const int* in_sizes, int n_in,
                              void* d_out, int out_size) {
    const float* x = (const float*)d_in[0];
    const float* k = (const float*)d_in[1];
    float* out = (float*)d_out;
    dim3 grid(112, NN);   // 56 row-pairs x 2 strips
    bconv_kernel<<<grid, 128>>>(x, k, out);
}